// round 14
// baseline (speedup 1.0000x reference)
#include <cuda_runtime.h>

#define BATCH 16
#define CIN   256
#define HW    4096
#define DDIM  128
#define CCL   32
#define EPSV  1e-8f
#define NF    ((long)BATCH * CIN * HW)

#define KC    32
#define NCH   8
#define NKLD  16
#define GEMM_BLKS 512

// ---- smem layout (bytes), 3 pipeline stages ----
// stage: A pane 256 rows x 144B  +  B pane 32 rows x 544B
#define PANEA_SZ 36864
#define PANEB_SZ 17408
#define STAGE_SZ (PANEA_SZ + PANEB_SZ)        // 54272
#define OFF_ZC   (3 * STAGE_SZ)               // 162816
#define OFF_BIAS (OFF_ZC + 512)               // 163328
#define SMEM_TOTAL (OFF_BIAS + 1024)          // 164352

__device__ float g_kld[BATCH];
__device__ int   g_cnt;

// ---------------------------------------------------------------------------
__device__ __forceinline__ unsigned smem_u32(const void* p) {
    unsigned a;
    asm("{ .reg .u64 t; cvta.to.shared.u64 t, %1; cvt.u32.u64 %0, t; }" : "=r"(a) : "l"(p));
    return a;
}
__device__ __forceinline__ void cp16(unsigned dst, const void* src) {
    asm volatile("cp.async.cg.shared.global [%0], [%1], 16;" :: "r"(dst), "l"(src));
}
#define CP_COMMIT() asm volatile("cp.async.commit_group;")
#define CP_WAIT(n)  asm volatile("cp.async.wait_group %0;" :: "n"(n))

__device__ __forceinline__ unsigned lds32(unsigned a) {
    unsigned v;
    asm volatile("ld.shared.b32 %0, [%1];" : "=r"(v) : "r"(a));
    return v;
}

__device__ __forceinline__ void mma_tf32(float* c, unsigned a0, unsigned a1,
                                         unsigned a2, unsigned a3,
                                         unsigned b0, unsigned b1) {
    asm volatile(
        "mma.sync.aligned.m16n8k8.row.col.f32.tf32.tf32.f32 "
        "{%0,%1,%2,%3}, {%4,%5,%6,%7}, {%8,%9}, {%0,%1,%2,%3};"
        : "+f"(c[0]), "+f"(c[1]), "+f"(c[2]), "+f"(c[3])
        : "r"(a0), "r"(a1), "r"(a2), "r"(a3), "r"(b0), "r"(b1));
}

// ---------------------------------------------------------------------------
// Fused kernel: blocks 0..15 KLD, blocks 16..527 GEMM tiles.
// ---------------------------------------------------------------------------
__global__ __launch_bounds__(512, 1)
void fused_kernel(const float* __restrict__ f,  const float* __restrict__ mu_prior,
                  const float* __restrict__ ls_prior, const float* __restrict__ pi_prior,
                  const float* __restrict__ mu_post,  const float* __restrict__ ls_post,
                  const float* __restrict__ noise_c,  const float* __restrict__ noise_z,
                  const float* __restrict__ W,        const float* __restrict__ pb,
                  float* __restrict__ out, int out_size)
{
    extern __shared__ __align__(16) char smem[];
    const int t = threadIdx.x;
    const int wid = t >> 5, lane = t & 31;

    if (blockIdx.x < NKLD) {
        // ------------------------- KLD blocks -------------------------
        const int b = blockIdx.x;
        float* S = (float*)smem;
        float* zpost = S;        float* mupo = S + 128;  float* lspo = S + 256;
        float* e2po  = S + 384;  float* kstd = S + 512;
        float* lps   = S + 640;  float* klgs = S + 896;
        if (t < DDIM) {
            float mu = mu_post[b * DDIM + t];
            float ls = ls_post[b * DDIM + t];
            float e  = expf(ls);
            mupo[t] = mu; lspo[t] = ls; e2po[t] = e * e;
            zpost[t] = mu + e * noise_c[b * DDIM + t];
            kstd[t]  = -ls + 0.5f * (e * e + mu * mu) - 0.5f;
        }
        __syncthreads();
        const int c = lane;
        if (wid < 8) {
            float lp = 0.f, klg = 0.f;
            #pragma unroll 4
            for (int j = 0; j < 16; j++) {
                int dd = wid * 16 + j;
                long idx = ((long)b * DDIM + dd) * CCL + c;
                float mpr = mu_prior[idx];
                float lpr = ls_prior[idx];
                float s2x2 = 2.f * expf(2.f * lpr);
                float dz = zpost[dd] - mpr;
                lp += -lpr - 0.91893853320467274f - dz * dz / s2x2;
                float dm = mupo[dd] - mpr;
                klg += lpr - lspo[dd] + (e2po[dd] + dm * dm) / (s2x2 + EPSV) - 0.5f;
            }
            lps[wid * 32 + c] = lp; klgs[wid * 32 + c] = klg;
        }
        __syncthreads();
        if (wid == 0) {
            float LP = 0.f, KG = 0.f;
            #pragma unroll
            for (int j = 0; j < 8; j++) { LP += lps[j * 32 + c]; KG += klgs[j * 32 + c]; }
            float m = LP;
            #pragma unroll
            for (int o = 16; o; o >>= 1) m = fmaxf(m, __shfl_xor_sync(~0u, m, o));
            float e = expf(LP - m), s = e;
            #pragma unroll
            for (int o = 16; o; o >>= 1) s += __shfl_xor_sync(~0u, s, o);
            float pi = e / s;
            float term = pi * KG + pi * (logf(pi + EPSV) - logf(pi_prior[b * CCL + c] + EPSV));
            #pragma unroll
            for (int o = 16; o; o >>= 1) term += __shfl_xor_sync(~0u, term, o);
            float ks = kstd[c] + kstd[c + 32] + kstd[c + 64] + kstd[c + 96];
            #pragma unroll
            for (int o = 16; o; o >>= 1) ks += __shfl_xor_sync(~0u, ks, o);
            if (c == 0) g_kld[b] = term + ks;
        }
        __syncthreads();
        if (t == 0) {
            __threadfence();
            int old = atomicAdd(&g_cnt, 1);
            if (old == BATCH - 1) {
                __threadfence();
                float s = 0.f;
                #pragma unroll
                for (int bb = 0; bb < BATCH; bb++) s += g_kld[bb];
                s *= (1.f / BATCH);
                for (long i = NF; i < (long)out_size; i++) out[i] = s;
                atomicExch(&g_cnt, 0);
            }
        }
        return;
    }

    // ------------------------------ GEMM blocks ------------------------------
    const int gbid = blockIdx.x - NKLD;
    const int b  = gbid >> 5;
    const int p0 = (gbid & 31) << 7;
    const unsigned sb = smem_u32(smem);
    float* zc    = (float*)(smem + OFF_ZC);
    float* sbias = (float*)(smem + OFF_BIAS);

    const float* fb = f + (long)b * CIN * HW + p0;

    // cp.async a full chunk straight into stage panes (native orientation)
    auto issue = [&](int ch, int st) {
        unsigned pa = sb + st * STAGE_SZ;
        #pragma unroll
        for (int j = 0; j < 4; j++) {
            int id = t + j * 512, row = id >> 3, seg = id & 7;
            cp16(pa + row * 144 + seg * 16, W + (long)row * 384 + ch * KC + seg * 4);
        }
        unsigned pbn = pa + PANEA_SZ;
        #pragma unroll
        for (int j = 0; j < 2; j++) {
            int id = t + j * 512, row = id >> 5, seg = id & 31;
            cp16(pbn + row * 544 + seg * 16, fb + (long)(ch * KC + row) * HW + seg * 4);
        }
        CP_COMMIT();
    };

    // ---- prologue: fill 3-deep pipe (chunks 0,1,2) ----
    issue(0, 0);
    issue(1, 1);
    issue(2, 2);
    if (t < DDIM) {
        float mu = mu_post[b * DDIM + t];
        float ls = ls_post[b * DDIM + t];
        zc[t] = mu + (expf(ls) + EPSV) * noise_z[b * DDIM + t];
    }
    CP_WAIT(2);                       // chunk 0 landed
    __syncthreads();                  // pane0 + zc visible
    if (t < 256) {
        float acc = 0.f;
        const float* wz = W + (long)t * 384 + CIN;
        #pragma unroll
        for (int dd = 0; dd < DDIM; dd += 4) {
            float4 wv = *(const float4*)(wz + dd);
            acc += wv.x * zc[dd] + wv.y * zc[dd + 1] + wv.z * zc[dd + 2] + wv.w * zc[dd + 3];
        }
        sbias[t] = acc + pb[t];
    }

    float c[4][4][4];
    #pragma unroll
    for (int i = 0; i < 4; i++)
        #pragma unroll
        for (int j = 0; j < 4; j++)
            #pragma unroll
            for (int k = 0; k < 4; k++) c[i][j][k] = 0.f;

    const int wy = wid >> 2;          // o block (64 rows)
    const int wx = wid & 3;           // p block (32 cols)
    const unsigned r = lane >> 2, qq = lane & 3;
    const unsigned abase = (wy * 64 + r) * 144 + qq * 4;
    const unsigned bbase = qq * 544 + (wx * 32 + r) * 4;

    int st = 0;                       // stage of current chunk
    for (int ch = 0; ch < NCH; ch++) {
        const unsigned pa  = sb + st * STAGE_SZ;
        const unsigned pbn = pa + PANEA_SZ;

        #pragma unroll
        for (int ks = 0; ks < 4; ks++) {
            unsigned b0[4], b1[4];
            #pragma unroll
            for (int ni = 0; ni < 4; ni++) {
                unsigned ad = pbn + bbase + ks * 8 * 544 + ni * 32;
                b0[ni] = lds32(ad);
                b1[ni] = lds32(ad + 2176);
            }
            #pragma unroll
            for (int mi = 0; mi < 4; mi++) {
                unsigned aad = pa + abase + mi * 16 * 144 + ks * 32;
                unsigned a0 = lds32(aad);
                unsigned a1 = lds32(aad + 1152);
                unsigned a2 = lds32(aad + 16);
                unsigned a3 = lds32(aad + 1168);
                #pragma unroll
                for (int ni = 0; ni < 4; ni++)
                    mma_tf32(c[mi][ni], a0, a1, a2, a3, b0[ni], b1[ni]);
            }
        }

        if (ch < NCH - 1) {
            // guarantee chunk ch+1 landed: ch+2 may still be in flight
            if (ch < NCH - 2) CP_WAIT(1); else CP_WAIT(0);
            __syncthreads();          // publishes ch+1; retires all readers of st
            if (ch + 3 < NCH) issue(ch + 3, st);   // safe: st free after barrier
        }
        st = (st == 2) ? 0 : st + 1;
    }

    // ---- epilogue: bias add + store ----
    #pragma unroll
    for (int mi = 0; mi < 4; mi++) {
        #pragma unroll
        for (int h = 0; h < 2; h++) {
            int o = wy * 64 + mi * 16 + h * 8 + (int)r;
            float bias = sbias[o];
            float* row = out + ((long)(b * CIN + o)) * HW + p0 + wx * 32 + 2 * qq;
            #pragma unroll
            for (int ni = 0; ni < 4; ni++) {
                float2 v = make_float2(c[mi][ni][2 * h] + bias,
                                       c[mi][ni][2 * h + 1] + bias);
                *(float2*)(row + ni * 8) = v;
            }
        }
    }
}

// ---------------------------------------------------------------------------
extern "C" void kernel_launch(void* const* d_in, const int* in_sizes, int n_in,
                              void* d_out, int out_size)
{
    const float* f_curr   = (const float*)d_in[0];
    const float* mu_prior = (const float*)d_in[1];
    const float* ls_prior = (const float*)d_in[2];
    const float* pi_prior = (const float*)d_in[3];
    const float* mu_post  = (const float*)d_in[4];
    const float* ls_post  = (const float*)d_in[5];
    const float* noise_c  = (const float*)d_in[6];
    const float* noise_z  = (const float*)d_in[7];
    const float* W        = (const float*)d_in[8];
    const float* pb       = (const float*)d_in[9];
    float* out = (float*)d_out;

    cudaFuncSetAttribute(fused_kernel,
                         cudaFuncAttributeMaxDynamicSharedMemorySize, SMEM_TOTAL);
    fused_kernel<<<NKLD + GEMM_BLKS, 512, SMEM_TOTAL>>>(
        f_curr, mu_prior, ls_prior, pi_prior, mu_post, ls_post,
        noise_c, noise_z, W, pb, out, out_size);
}

// round 15
// speedup vs baseline: 1.2124x; 1.2124x over previous
#include <cuda_runtime.h>

#define BATCH 16
#define CIN   256
#define HW    4096
#define DDIM  128
#define CCL   32
#define EPSV  1e-8f
#define NF    ((long)BATCH * CIN * HW)

#define KC    32
#define NCH   8
#define NKLD  16
#define GEMM_BLKS 1024      // 16 b x 32 p x 2 o-halves

// ---- smem layout (bytes), 2 stages ----
// stage: A pane 128 rows x 144B (18432) + B pane 32 rows x 544B (17408)
#define PANEA_SZ 18432
#define PANEB_SZ 17408
#define STAGE_SZ (PANEA_SZ + PANEB_SZ)        // 35840
#define OFF_ZC   (2 * STAGE_SZ)               // 71680
#define OFF_BIAS (OFF_ZC + 512)               // 72192
#define SMEM_TOTAL (OFF_BIAS + 512)           // 72704

__device__ float g_kld[BATCH];
__device__ int   g_cnt;

// ---------------------------------------------------------------------------
__device__ __forceinline__ unsigned smem_u32(const void* p) {
    unsigned a;
    asm("{ .reg .u64 t; cvta.to.shared.u64 t, %1; cvt.u32.u64 %0, t; }" : "=r"(a) : "l"(p));
    return a;
}
__device__ __forceinline__ void cp16(unsigned dst, const void* src) {
    asm volatile("cp.async.cg.shared.global [%0], [%1], 16;" :: "r"(dst), "l"(src));
}
#define CP_COMMIT() asm volatile("cp.async.commit_group;")
#define CP_WAIT(n)  asm volatile("cp.async.wait_group %0;" :: "n"(n))

__device__ __forceinline__ unsigned lds32(unsigned a) {
    unsigned v;
    asm volatile("ld.shared.b32 %0, [%1];" : "=r"(v) : "r"(a));
    return v;
}

__device__ __forceinline__ void mma_tf32(float* c, unsigned a0, unsigned a1,
                                         unsigned a2, unsigned a3,
                                         unsigned b0, unsigned b1) {
    asm volatile(
        "mma.sync.aligned.m16n8k8.row.col.f32.tf32.tf32.f32 "
        "{%0,%1,%2,%3}, {%4,%5,%6,%7}, {%8,%9}, {%0,%1,%2,%3};"
        : "+f"(c[0]), "+f"(c[1]), "+f"(c[2]), "+f"(c[3])
        : "r"(a0), "r"(a1), "r"(a2), "r"(a3), "r"(b0), "r"(b1));
}

// ---------------------------------------------------------------------------
// Fused kernel: blocks 0..15 KLD, blocks 16..1039 GEMM (O=128 x P=128 tiles).
// 256 threads/CTA -> 2 CTAs/SM: two independent barrier domains per SM.
// ---------------------------------------------------------------------------
__global__ __launch_bounds__(256, 2)
void fused_kernel(const float* __restrict__ f,  const float* __restrict__ mu_prior,
                  const float* __restrict__ ls_prior, const float* __restrict__ pi_prior,
                  const float* __restrict__ mu_post,  const float* __restrict__ ls_post,
                  const float* __restrict__ noise_c,  const float* __restrict__ noise_z,
                  const float* __restrict__ W,        const float* __restrict__ pb,
                  float* __restrict__ out, int out_size)
{
    extern __shared__ __align__(16) char smem[];
    const int t = threadIdx.x;
    const int wid = t >> 5, lane = t & 31;

    if (blockIdx.x < NKLD) {
        // ------------------------- KLD blocks (256 thr = 8 warps) ----------
        const int b = blockIdx.x;
        float* S = (float*)smem;
        float* zpost = S;        float* mupo = S + 128;  float* lspo = S + 256;
        float* e2po  = S + 384;  float* kstd = S + 512;
        float* lps   = S + 640;  float* klgs = S + 896;
        if (t < DDIM) {
            float mu = mu_post[b * DDIM + t];
            float ls = ls_post[b * DDIM + t];
            float e  = expf(ls);
            mupo[t] = mu; lspo[t] = ls; e2po[t] = e * e;
            zpost[t] = mu + e * noise_c[b * DDIM + t];
            kstd[t]  = -ls + 0.5f * (e * e + mu * mu) - 0.5f;
        }
        __syncthreads();
        const int c = lane;
        {
            float lp = 0.f, klg = 0.f;
            #pragma unroll 4
            for (int j = 0; j < 16; j++) {
                int dd = wid * 16 + j;
                long idx = ((long)b * DDIM + dd) * CCL + c;
                float mpr = mu_prior[idx];
                float lpr = ls_prior[idx];
                float s2x2 = 2.f * expf(2.f * lpr);
                float dz = zpost[dd] - mpr;
                lp += -lpr - 0.91893853320467274f - dz * dz / s2x2;
                float dm = mupo[dd] - mpr;
                klg += lpr - lspo[dd] + (e2po[dd] + dm * dm) / (s2x2 + EPSV) - 0.5f;
            }
            lps[wid * 32 + c] = lp; klgs[wid * 32 + c] = klg;
        }
        __syncthreads();
        if (wid == 0) {
            float LP = 0.f, KG = 0.f;
            #pragma unroll
            for (int j = 0; j < 8; j++) { LP += lps[j * 32 + c]; KG += klgs[j * 32 + c]; }
            float m = LP;
            #pragma unroll
            for (int o = 16; o; o >>= 1) m = fmaxf(m, __shfl_xor_sync(~0u, m, o));
            float e = expf(LP - m), s = e;
            #pragma unroll
            for (int o = 16; o; o >>= 1) s += __shfl_xor_sync(~0u, s, o);
            float pi = e / s;
            float term = pi * KG + pi * (logf(pi + EPSV) - logf(pi_prior[b * CCL + c] + EPSV));
            #pragma unroll
            for (int o = 16; o; o >>= 1) term += __shfl_xor_sync(~0u, term, o);
            float ks = kstd[c] + kstd[c + 32] + kstd[c + 64] + kstd[c + 96];
            #pragma unroll
            for (int o = 16; o; o >>= 1) ks += __shfl_xor_sync(~0u, ks, o);
            if (c == 0) g_kld[b] = term + ks;
        }
        __syncthreads();
        if (t == 0) {
            __threadfence();
            int old = atomicAdd(&g_cnt, 1);
            if (old == BATCH - 1) {
                __threadfence();
                float s = 0.f;
                #pragma unroll
                for (int bb = 0; bb < BATCH; bb++) s += g_kld[bb];
                s *= (1.f / BATCH);
                for (long i = NF; i < (long)out_size; i++) out[i] = s;
                atomicExch(&g_cnt, 0);
            }
        }
        return;
    }

    // ------------------------------ GEMM blocks ------------------------------
    const int gbid = blockIdx.x - NKLD;
    const int b   = gbid >> 6;
    const int oh  = gbid & 1;                 // o-half; twins adjacent -> L2 reuse
    const int pt  = (gbid >> 1) & 31;
    const int o0  = oh << 7, p0 = pt << 7;

    const unsigned sb = smem_u32(smem);
    float* zc    = (float*)(smem + OFF_ZC);
    float* sbias = (float*)(smem + OFF_BIAS);

    const float* fb = f + (long)b * CIN * HW + p0;

    // cp.async a full chunk into stage panes (native orientation)
    auto issue = [&](int ch, int st) {
        unsigned pa = sb + st * STAGE_SZ;
        #pragma unroll
        for (int j = 0; j < 4; j++) {          // A: 128 rows x 8 segs
            int id = t + j * 256, row = id >> 3, seg = id & 7;
            cp16(pa + row * 144 + seg * 16,
                 W + (long)(o0 + row) * 384 + ch * KC + seg * 4);
        }
        unsigned pbn = pa + PANEA_SZ;
        #pragma unroll
        for (int j = 0; j < 4; j++) {          // B: 32 rows x 32 segs
            int id = t + j * 256, row = id >> 5, seg = id & 31;
            cp16(pbn + row * 544 + seg * 16,
                 fb + (long)(ch * KC + row) * HW + seg * 4);
        }
        CP_COMMIT();
    };

    // ---- prologue ----
    issue(0, 0);
    issue(1, 1);
    if (t < DDIM) {
        float mu = mu_post[b * DDIM + t];
        float ls = ls_post[b * DDIM + t];
        zc[t] = mu + (expf(ls) + EPSV) * noise_z[b * DDIM + t];
    }
    CP_WAIT(1);
    __syncthreads();                  // pane0 + zc visible
    if (t < 128) {
        float acc = 0.f;
        const float* wz = W + (long)(o0 + t) * 384 + CIN;
        #pragma unroll
        for (int dd = 0; dd < DDIM; dd += 4) {
            float4 wv = *(const float4*)(wz + dd);
            acc += wv.x * zc[dd] + wv.y * zc[dd + 1] + wv.z * zc[dd + 2] + wv.w * zc[dd + 3];
        }
        sbias[t] = acc + pb[o0 + t];
    }

    float c[4][4][4];
    #pragma unroll
    for (int i = 0; i < 4; i++)
        #pragma unroll
        for (int j = 0; j < 4; j++)
            #pragma unroll
            for (int k = 0; k < 4; k++) c[i][j][k] = 0.f;

    const int wy = wid >> 2;          // o block (64 rows): 0..1
    const int wx = wid & 3;           // p block (32 cols): 0..3
    const unsigned r = lane >> 2, qq = lane & 3;
    const unsigned abase = (wy * 64 + r) * 144 + qq * 4;
    const unsigned bbase = qq * 544 + (wx * 32 + r) * 4;

    for (int ch = 0; ch < NCH; ch++) {
        const int par = ch & 1;
        const unsigned pa  = sb + par * STAGE_SZ;
        const unsigned pbn = pa + PANEA_SZ;

        #pragma unroll
        for (int ks = 0; ks < 4; ks++) {
            unsigned b0[4], b1[4];
            #pragma unroll
            for (int ni = 0; ni < 4; ni++) {
                unsigned ad = pbn + bbase + ks * 8 * 544 + ni * 32;
                b0[ni] = lds32(ad);
                b1[ni] = lds32(ad + 2176);
            }
            #pragma unroll
            for (int mi = 0; mi < 4; mi++) {
                unsigned aad = pa + abase + mi * 16 * 144 + ks * 32;
                unsigned a0 = lds32(aad);
                unsigned a1 = lds32(aad + 1152);
                unsigned a2 = lds32(aad + 16);
                unsigned a3 = lds32(aad + 1168);
                #pragma unroll
                for (int ni = 0; ni < 4; ni++)
                    mma_tf32(c[mi][ni], a0, a1, a2, a3, b0[ni], b1[ni]);
            }
        }

        if (ch < NCH - 1) {
            CP_WAIT(0);               // chunk ch+1 landed
            __syncthreads();          // publishes ch+1; retires readers of pane[par]
            if (ch < NCH - 2) issue(ch + 2, par);
        }
    }

    // ---- epilogue: bias add + store ----
    #pragma unroll
    for (int mi = 0; mi < 4; mi++) {
        #pragma unroll
        for (int h = 0; h < 2; h++) {
            int ol = wy * 64 + mi * 16 + h * 8 + (int)r;
            float bias = sbias[ol];
            float* row = out + ((long)(b * CIN + o0 + ol)) * HW + p0 + wx * 32 + 2 * qq;
            #pragma unroll
            for (int ni = 0; ni < 4; ni++) {
                float2 v = make_float2(c[mi][ni][2 * h] + bias,
                                       c[mi][ni][2 * h + 1] + bias);
                *(float2*)(row + ni * 8) = v;
            }
        }
    }
}

// ---------------------------------------------------------------------------
extern "C" void kernel_launch(void* const* d_in, const int* in_sizes, int n_in,
                              void* d_out, int out_size)
{
    const float* f_curr   = (const float*)d_in[0];
    const float* mu_prior = (const float*)d_in[1];
    const float* ls_prior = (const float*)d_in[2];
    const float* pi_prior = (const float*)d_in[3];
    const float* mu_post  = (const float*)d_in[4];
    const float* ls_post  = (const float*)d_in[5];
    const float* noise_c  = (const float*)d_in[6];
    const float* noise_z  = (const float*)d_in[7];
    const float* W        = (const float*)d_in[8];
    const float* pb       = (const float*)d_in[9];
    float* out = (float*)d_out;

    cudaFuncSetAttribute(fused_kernel,
                         cudaFuncAttributeMaxDynamicSharedMemorySize, SMEM_TOTAL);
    fused_kernel<<<NKLD + GEMM_BLKS, 256, SMEM_TOTAL>>>(
        f_curr, mu_prior, ls_prior, pi_prior, mu_post, ls_post,
        noise_c, noise_z, W, pb, out, out_size);
}